// round 6
// baseline (speedup 1.0000x reference)
#include <cuda_runtime.h>

// Float32HardwareSurrogate — warp-shuffle version, SEL-free reduce-scatter.
//
// Coalesced float4 loads (idx = lane + 32k) put one complete image per
// 16-lane group each iteration: lane e holds float4 element e of image
// 2k + (lane>>4). Element e -> quadrant q = ((e>>3)<<1)|(e&1), quadrant-row
// rr = (e>>1)&3, pixels = quadrant-row rr, cols 0..3.
//
// Stage 1: lane partial P over 4 conv channels; reduce-scatter over the 4
// holder lanes (xor4, xor2) leaves lane e with scalar c[K], K=q*4+rr.
// Stage 2: T = clip(relu(c)/64)*Wl[K][:]; reduce-scatter over 16 lanes
// (xor8, xor4, then plain xor2/xor1) leaves output component ncomp.
//
// SEL-free trick: weights are loaded with a per-lane XOR column permutation
// (Wc position p holds channel rr^p; Wl position p holds output ncomp^p), so
// every scatter step is unconditionally keep(x,y)/send(z,w) then keep(A)/
// send(B). The partner lane (differing in the corresponding rr/ncomp bit)
// provably sends exactly the channels this lane keeps. Same addition tree as
// the previous passing kernel -> identical numerics.

#define THREADS 256
#define WARPS_PER_BLOCK 8
#define IMGS_PER_WARP 32

__global__ void __launch_bounds__(THREADS, 4)
surrogate_kernel(const float* __restrict__ img1,
                 const float* __restrict__ img2,
                 const float* __restrict__ Wc,
                 const float* __restrict__ Wl,
                 float* __restrict__ out,
                 int nimg)
{
    const int lane = threadIdx.x & 31;
    const int warp = threadIdx.x >> 5;
    const long wg  = (long)blockIdx.x * WARPS_PER_BLOCK + warp;
    const long g0  = wg * IMGS_PER_WARP;
    const long total = 2L * (long)nimg;
    if (g0 >= total) return;

    // nimg is a multiple of 32 -> warp never straddles img1/img2.
    const float4* __restrict__ src = (const float4*)(
        (g0 < (long)nimg) ? (img1 + g0 * 64)
                          : (img2 + (g0 - (long)nimg) * 64));

    // ---- per-lane constants ----
    const int e     = lane & 15;
    const int g     = lane >> 4;                  // image parity within pair
    const int rr    = (e >> 1) & 3;               // row within quadrant
    const int q     = ((e >> 3) << 1) | (e & 1);  // quadrant TL,TR,BL,BR
    const int K     = q * 4 + rr;                 // c-index this lane owns
    const int ncomp = 2 * ((e >> 3) & 1) + ((e >> 2) & 1);  // owned output comp
    const bool do_store = ((e & 3) == 0);

    // ---- per-lane XOR-permuted weights ----
    // wc[c] position p = Wc[rr*4+c][rr^p]; wl position p = Wl[K][ncomp^p].
    float4 wc0, wc1, wc2, wc3, wl;
    {
        const float* r0 = Wc + (rr * 4 + 0) * 4;
        const float* r1 = Wc + (rr * 4 + 1) * 4;
        const float* r2 = Wc + (rr * 4 + 2) * 4;
        const float* r3 = Wc + (rr * 4 + 3) * 4;
        wc0 = make_float4(r0[rr], r0[rr ^ 1], r0[rr ^ 2], r0[rr ^ 3]);
        wc1 = make_float4(r1[rr], r1[rr ^ 1], r1[rr ^ 2], r1[rr ^ 3]);
        wc2 = make_float4(r2[rr], r2[rr ^ 1], r2[rr ^ 2], r2[rr ^ 3]);
        wc3 = make_float4(r3[rr], r3[rr ^ 1], r3[rr ^ 2], r3[rr ^ 3]);
        const float* rl = Wl + K * 4;
        wl  = make_float4(rl[ncomp], rl[ncomp ^ 1], rl[ncomp ^ 2], rl[ncomp ^ 3]);
    }

    const float inv64 = 0.015625f;
    const unsigned FULL = 0xffffffffu;
    // store base: image g0+g, component ncomp; advances 8 floats per iteration
    float* __restrict__ outp = out + (g0 + g) * 4 + ncomp;

    #pragma unroll
    for (int kb = 0; kb < 4; ++kb) {
        float4 v[4];
        #pragma unroll
        for (int t = 0; t < 4; ++t)
            v[t] = src[lane + 32 * (kb * 4 + t)];

        #pragma unroll
        for (int t = 0; t < 4; ++t) {
            const int k = kb * 4 + t;

            // Stage 1 partials (position p = channel rr^p)
            float4 P;
            P.x = v[t].x * wc0.x; P.y = v[t].x * wc0.y;
            P.z = v[t].x * wc0.z; P.w = v[t].x * wc0.w;
            P.x = fmaf(v[t].y, wc1.x, P.x); P.y = fmaf(v[t].y, wc1.y, P.y);
            P.z = fmaf(v[t].y, wc1.z, P.z); P.w = fmaf(v[t].y, wc1.w, P.w);
            P.x = fmaf(v[t].z, wc2.x, P.x); P.y = fmaf(v[t].z, wc2.y, P.y);
            P.z = fmaf(v[t].z, wc2.z, P.z); P.w = fmaf(v[t].z, wc2.w, P.w);
            P.x = fmaf(v[t].w, wc3.x, P.x); P.y = fmaf(v[t].w, wc3.y, P.y);
            P.z = fmaf(v[t].w, wc3.z, P.z); P.w = fmaf(v[t].w, wc3.w, P.w);

            // SEL-free reduce-scatter over quadrant lanes: keep(x,y) send(z,w)
            float A  = P.x + __shfl_xor_sync(FULL, P.z, 4);
            float Bv = P.y + __shfl_xor_sync(FULL, P.w, 4);
            float c1 = A   + __shfl_xor_sync(FULL, Bv,  2);

            // relu -> /64 -> upper clip (lower clip dead after relu)
            float cv = fminf(fmaxf(c1, 0.0f) * inv64, 127.0f);

            // Stage 2 partials (position p = output ncomp^p)
            float Tx = cv * wl.x, Ty = cv * wl.y;
            float Tz = cv * wl.z, Tw = cv * wl.w;

            // SEL-free reduce-scatter over 16 lanes
            float A2 = Tx + __shfl_xor_sync(FULL, Tz, 8);
            float B2 = Ty + __shfl_xor_sync(FULL, Tw, 8);
            float sc = A2 + __shfl_xor_sync(FULL, B2, 4);
            sc += __shfl_xor_sync(FULL, sc, 2);
            sc += __shfl_xor_sync(FULL, sc, 1);

            float o = fminf(fmaxf(sc * inv64, -128.0f), 127.0f);

            // lanes {0,4,8,12}(+16): 8 lanes, 32 contiguous bytes
            if (do_store)
                outp[8 * k] = o;
        }
    }
}

extern "C" void kernel_launch(void* const* d_in, const int* in_sizes, int n_in,
                              void* d_out, int out_size) {
    const float* img1 = (const float*)d_in[0];
    const float* img2 = (const float*)d_in[1];
    const float* Wc   = (const float*)d_in[2];
    const float* Wl   = (const float*)d_in[3];
    float* out        = (float*)d_out;

    int nimg = in_sizes[0] / 64;                       // B
    long total_imgs = 2L * (long)nimg;
    long total_warps = (total_imgs + IMGS_PER_WARP - 1) / IMGS_PER_WARP;
    int nblocks = (int)((total_warps + WARPS_PER_BLOCK - 1) / WARPS_PER_BLOCK);

    surrogate_kernel<<<nblocks, THREADS>>>(img1, img2, Wc, Wl, out, nimg);
}

// round 7
// speedup vs baseline: 1.0021x; 1.0021x over previous
#include <cuda_runtime.h>

// Float32HardwareSurrogate — warp-shuffle, SEL-free reduce-scatter,
// software-pipelined loads (rolling window of 8 LDG.128 in flight).
//
// Coalesced float4 loads (idx = lane + 32k) put one complete image per
// 16-lane group each iteration: lane e holds float4 element e of image
// 2k + (lane>>4). Element e -> quadrant q=((e>>3)<<1)|(e&1), quadrant-row
// rr=(e>>1)&3.
//
// Stage 1: partial over 4 conv channels; reduce-scatter (xor4 x2, xor2)
// leaves lane e with scalar c[K], K=q*4+rr. Stage 2: T=clip(relu(c)/64)*Wl[K];
// reduce-scatter (xor8 x2, xor4, xor2, xor1) leaves output comp ncomp.
// Weights are pre-permuted per lane (pos p = channel rr^p / output ncomp^p)
// so every scatter step is unconditionally keep(x,y)/send(z,w) — zero SELs
// in the hot loop. Same addition tree as the R4/R5 passing kernels.

#define THREADS 256
#define WARPS_PER_BLOCK 8
#define IMGS_PER_WARP 32

// XOR-permute float4 components: result pos p = w[bits ^ p]. SELs, prologue-only.
__device__ __forceinline__ float4 xorperm(float4 w, int bits) {
    float t;
    if (bits & 2) { t = w.x; w.x = w.z; w.z = t; t = w.y; w.y = w.w; w.w = t; }
    if (bits & 1) { t = w.x; w.x = w.y; w.y = t; t = w.z; w.z = w.w; w.w = t; }
    return w;
}

__global__ void __launch_bounds__(THREADS, 4)
surrogate_kernel(const float* __restrict__ img1,
                 const float* __restrict__ img2,
                 const float* __restrict__ Wc,
                 const float* __restrict__ Wl,
                 float* __restrict__ out,
                 int nimg)
{
    const int lane = threadIdx.x & 31;
    const int warp = threadIdx.x >> 5;
    const long wg  = (long)blockIdx.x * WARPS_PER_BLOCK + warp;
    const long g0  = wg * IMGS_PER_WARP;
    const long total = 2L * (long)nimg;
    if (g0 >= total) return;

    // nimg is a multiple of 32 -> warp never straddles img1/img2.
    const float4* __restrict__ src = (const float4*)(
        (g0 < (long)nimg) ? (img1 + g0 * 64)
                          : (img2 + (g0 - (long)nimg) * 64));

    const int e     = lane & 15;
    const int g     = lane >> 4;
    const int rr    = (e >> 1) & 3;
    const int q     = ((e >> 3) << 1) | (e & 1);
    const int K     = q * 4 + rr;
    const int ncomp = 2 * ((e >> 3) & 1) + ((e >> 2) & 1);
    const bool do_store = ((e & 3) == 0);

    // Vector weight loads + one-time per-lane XOR permutation.
    const float4* __restrict__ Wc4 = (const float4*)Wc;
    const float4* __restrict__ Wl4 = (const float4*)Wl;
    const float4 wc0 = xorperm(Wc4[rr * 4 + 0], rr);
    const float4 wc1 = xorperm(Wc4[rr * 4 + 1], rr);
    const float4 wc2 = xorperm(Wc4[rr * 4 + 2], rr);
    const float4 wc3 = xorperm(Wc4[rr * 4 + 3], rr);
    const float4 wl  = xorperm(Wl4[K], ncomp);

    const float inv64 = 0.015625f;
    const unsigned FULL = 0xffffffffu;
    float* __restrict__ outp = out + (g0 + g) * 4 + ncomp;

    // ---- compute one image pair from float4 v at iteration k ----
    #define COMPUTE_STORE(v_, k_)                                              \
    do {                                                                       \
        float4 P;                                                              \
        P.x = (v_).x * wc0.x; P.y = (v_).x * wc0.y;                            \
        P.z = (v_).x * wc0.z; P.w = (v_).x * wc0.w;                            \
        P.x = fmaf((v_).y, wc1.x, P.x); P.y = fmaf((v_).y, wc1.y, P.y);        \
        P.z = fmaf((v_).y, wc1.z, P.z); P.w = fmaf((v_).y, wc1.w, P.w);        \
        P.x = fmaf((v_).z, wc2.x, P.x); P.y = fmaf((v_).z, wc2.y, P.y);        \
        P.z = fmaf((v_).z, wc2.z, P.z); P.w = fmaf((v_).z, wc2.w, P.w);        \
        P.x = fmaf((v_).w, wc3.x, P.x); P.y = fmaf((v_).w, wc3.y, P.y);        \
        P.z = fmaf((v_).w, wc3.z, P.z); P.w = fmaf((v_).w, wc3.w, P.w);        \
        float A  = P.x + __shfl_xor_sync(FULL, P.z, 4);                        \
        float Bv = P.y + __shfl_xor_sync(FULL, P.w, 4);                        \
        float c1 = A   + __shfl_xor_sync(FULL, Bv,  2);                        \
        float cv = fminf(fmaxf(c1, 0.0f) * inv64, 127.0f);                     \
        float Tx = cv * wl.x, Ty = cv * wl.y;                                  \
        float Tz = cv * wl.z, Tw = cv * wl.w;                                  \
        float A2 = Tx + __shfl_xor_sync(FULL, Tz, 8);                          \
        float B2 = Ty + __shfl_xor_sync(FULL, Tw, 8);                          \
        float sc = A2 + __shfl_xor_sync(FULL, B2, 4);                          \
        sc += __shfl_xor_sync(FULL, sc, 2);                                    \
        sc += __shfl_xor_sync(FULL, sc, 1);                                    \
        float o = fminf(fmaxf(sc * inv64, -128.0f), 127.0f);                   \
        if (do_store) outp[8 * (k_)] = o;                                      \
    } while (0)

    // Rolling-window software pipeline: 8 loads in flight.
    float4 v[8];
    #pragma unroll
    for (int k = 0; k < 8; ++k)
        v[k] = src[lane + 32 * k];

    #pragma unroll
    for (int k = 0; k < 8; ++k) {
        float4 cur = v[k];
        v[k] = src[lane + 32 * (k + 8)];   // prefetch second half
        COMPUTE_STORE(cur, k);
    }

    #pragma unroll
    for (int k = 0; k < 8; ++k)
        COMPUTE_STORE(v[k], k + 8);

    #undef COMPUTE_STORE
}

extern "C" void kernel_launch(void* const* d_in, const int* in_sizes, int n_in,
                              void* d_out, int out_size) {
    const float* img1 = (const float*)d_in[0];
    const float* img2 = (const float*)d_in[1];
    const float* Wc   = (const float*)d_in[2];
    const float* Wl   = (const float*)d_in[3];
    float* out        = (float*)d_out;

    int nimg = in_sizes[0] / 64;                       // B
    long total_imgs = 2L * (long)nimg;
    long total_warps = (total_imgs + IMGS_PER_WARP - 1) / IMGS_PER_WARP;
    int nblocks = (int)((total_warps + WARPS_PER_BLOCK - 1) / WARPS_PER_BLOCK);

    surrogate_kernel<<<nblocks, THREADS>>>(img1, img2, Wc, Wl, out, nimg);
}

// round 11
// speedup vs baseline: 1.0513x; 1.0491x over previous
#include <cuda_runtime.h>

// Float32HardwareSurrogate — warp-shuffle, SEL-free reduce-scatter,
// occupancy-optimized: 51-reg cap -> 40 warps/SM (62.5%), window-4 ring
// prefetch, streaming cache hints (read/write-once data).
//
// Coalesced float4 loads (idx = lane + 32k) put one complete image per
// 16-lane group each iteration: lane e holds float4 element e of image
// 2k + (lane>>4). Element e -> quadrant q=((e>>3)<<1)|(e&1), quadrant-row
// rr=(e>>1)&3.
//
// Stage 1: partial over 4 conv channels; reduce-scatter (xor4 x2, xor2)
// leaves lane e with scalar c[K], K=q*4+rr. Stage 2: T=clip(relu(c)/64)*Wl[K];
// reduce-scatter (xor8 x2, xor4, xor2, xor1) leaves output comp ncomp.
// Weights are pre-permuted per lane (pos p = channel rr^p / output ncomp^p)
// so every scatter step is unconditionally keep(x,y)/send(z,w) — zero SELs
// in the hot loop. Same addition tree as the R4-R6 passing kernels.

#define THREADS 256
#define WARPS_PER_BLOCK 8
#define IMGS_PER_WARP 32

// XOR-permute float4 components: result pos p = w[bits ^ p]. Prologue-only.
__device__ __forceinline__ float4 xorperm(float4 w, int bits) {
    float t;
    if (bits & 2) { t = w.x; w.x = w.z; w.z = t; t = w.y; w.y = w.w; w.w = t; }
    if (bits & 1) { t = w.x; w.x = w.y; w.y = t; t = w.z; w.z = w.w; w.w = t; }
    return w;
}

__global__ void __launch_bounds__(THREADS, 5)   // 51-reg cap -> 40 warps/SM
surrogate_kernel(const float* __restrict__ img1,
                 const float* __restrict__ img2,
                 const float* __restrict__ Wc,
                 const float* __restrict__ Wl,
                 float* __restrict__ out,
                 int nimg)
{
    const int lane = threadIdx.x & 31;
    const int warp = threadIdx.x >> 5;
    const long wg  = (long)blockIdx.x * WARPS_PER_BLOCK + warp;
    const long g0  = wg * IMGS_PER_WARP;
    const long total = 2L * (long)nimg;
    if (g0 >= total) return;

    // nimg is a multiple of 32 -> warp never straddles img1/img2.
    const float4* __restrict__ src = (const float4*)(
        (g0 < (long)nimg) ? (img1 + g0 * 64)
                          : (img2 + (g0 - (long)nimg) * 64));

    const int e     = lane & 15;
    const int g     = lane >> 4;
    const int rr    = (e >> 1) & 3;
    const int q     = ((e >> 3) << 1) | (e & 1);
    const int K     = q * 4 + rr;
    const int ncomp = 2 * ((e >> 3) & 1) + ((e >> 2) & 1);
    const bool do_store = ((e & 3) == 0);

    // Vector weight loads + one-time per-lane XOR permutation.
    const float4* __restrict__ Wc4 = (const float4*)Wc;
    const float4* __restrict__ Wl4 = (const float4*)Wl;
    const float4 wc0 = xorperm(Wc4[rr * 4 + 0], rr);
    const float4 wc1 = xorperm(Wc4[rr * 4 + 1], rr);
    const float4 wc2 = xorperm(Wc4[rr * 4 + 2], rr);
    const float4 wc3 = xorperm(Wc4[rr * 4 + 3], rr);
    const float4 wl  = xorperm(Wl4[K], ncomp);

    const float inv64 = 0.015625f;
    const unsigned FULL = 0xffffffffu;
    float* __restrict__ outp = out + (g0 + g) * 4 + ncomp;

    #define COMPUTE_STORE(v_, k_)                                              \
    do {                                                                       \
        float4 P;                                                              \
        P.x = (v_).x * wc0.x; P.y = (v_).x * wc0.y;                            \
        P.z = (v_).x * wc0.z; P.w = (v_).x * wc0.w;                            \
        P.x = fmaf((v_).y, wc1.x, P.x); P.y = fmaf((v_).y, wc1.y, P.y);        \
        P.z = fmaf((v_).y, wc1.z, P.z); P.w = fmaf((v_).y, wc1.w, P.w);        \
        P.x = fmaf((v_).z, wc2.x, P.x); P.y = fmaf((v_).z, wc2.y, P.y);        \
        P.z = fmaf((v_).z, wc2.z, P.z); P.w = fmaf((v_).z, wc2.w, P.w);        \
        P.x = fmaf((v_).w, wc3.x, P.x); P.y = fmaf((v_).w, wc3.y, P.y);        \
        P.z = fmaf((v_).w, wc3.z, P.z); P.w = fmaf((v_).w, wc3.w, P.w);        \
        float A  = P.x + __shfl_xor_sync(FULL, P.z, 4);                        \
        float Bv = P.y + __shfl_xor_sync(FULL, P.w, 4);                        \
        float c1 = A   + __shfl_xor_sync(FULL, Bv,  2);                        \
        float cv = fminf(fmaxf(c1, 0.0f) * inv64, 127.0f);                     \
        float Tx = cv * wl.x, Ty = cv * wl.y;                                  \
        float Tz = cv * wl.z, Tw = cv * wl.w;                                  \
        float A2 = Tx + __shfl_xor_sync(FULL, Tz, 8);                          \
        float B2 = Ty + __shfl_xor_sync(FULL, Tw, 8);                          \
        float sc = A2 + __shfl_xor_sync(FULL, B2, 4);                          \
        sc += __shfl_xor_sync(FULL, sc, 2);                                    \
        sc += __shfl_xor_sync(FULL, sc, 1);                                    \
        float o = fminf(fmaxf(sc * inv64, -128.0f), 127.0f);                   \
        if (do_store) __stcs(outp + 8 * (k_), o);                              \
    } while (0)

    // Ring software pipeline, window 4: one prefetch interleaved per compute
    // block (spreads LDG issue; 16 regs for the window instead of 32).
    float4 v[4];
    #pragma unroll
    for (int k = 0; k < 4; ++k)
        v[k] = __ldcs(&src[lane + 32 * k]);

    #pragma unroll
    for (int k = 0; k < 16; ++k) {
        float4 cur = v[k & 3];
        if (k < 12)
            v[k & 3] = __ldcs(&src[lane + 32 * (k + 4)]);
        COMPUTE_STORE(cur, k);
    }

    #undef COMPUTE_STORE
}

extern "C" void kernel_launch(void* const* d_in, const int* in_sizes, int n_in,
                              void* d_out, int out_size) {
    const float* img1 = (const float*)d_in[0];
    const float* img2 = (const float*)d_in[1];
    const float* Wc   = (const float*)d_in[2];
    const float* Wl   = (const float*)d_in[3];
    float* out        = (float*)d_out;

    int nimg = in_sizes[0] / 64;                       // B
    long total_imgs = 2L * (long)nimg;
    long total_warps = (total_imgs + IMGS_PER_WARP - 1) / IMGS_PER_WARP;
    int nblocks = (int)((total_warps + WARPS_PER_BLOCK - 1) / WARPS_PER_BLOCK);

    surrogate_kernel<<<nblocks, THREADS>>>(img1, img2, Wc, Wl, out, nimg);
}